// round 12
// baseline (speedup 1.0000x reference)
#include <cuda_runtime.h>
#include <stdint.h>
#include <math.h>

#define BATCH 32
#define SEQ   8400
#define NLAB  80
#define DIM   256
#define NQ    300
#define CAND  512
#define RPB   128     // rows per block in scores kernel (512 thr, 5 ld/thread)
#define NTOPK BATCH   // topk blocks at the head of the combined grid
#define NGATH ((BATCH * NQ) / 8)   // 1200 gather blocks (8 queries each)

// Scratch (allocation-free per harness rules)
__device__ unsigned int g_scores_u[BATCH * SEQ];
__device__ int          g_topk[BATCH * NQ];
__device__ unsigned int g_flag[BATCH];            // zero-init; reset by scores

__device__ __forceinline__ unsigned int f32_sortable(float v) {
    unsigned int u = __float_as_uint(v);
    return (u & 0x80000000u) ? ~u : (u | 0x80000000u);
}

__device__ __forceinline__ void stg_cs_f4(float* p, float4 v) {
    asm volatile("st.global.cs.v4.f32 [%0], {%1,%2,%3,%4};"
                 :: "l"(p), "f"(v.x), "f"(v.y), "f"(v.z), "f"(v.w) : "memory");
}
__device__ __forceinline__ unsigned int ld_acquire(const unsigned int* p) {
    unsigned int v;
    asm volatile("ld.acquire.gpu.u32 %0, [%1];" : "=r"(v) : "l"(p) : "memory");
    return v;
}
__device__ __forceinline__ int ld_cg_s32(const int* p) {
    int v;
    asm volatile("ld.global.cg.s32 %0, [%1];" : "=r"(v) : "l"(p));
    return v;
}

// ---------------------------------------------------------------------------
// Kernel 1: scores (best measured: 512 thr, 5 float4/thread, smem transpose).
// Block 0 also resets the handshake flags (kernel boundary = fence).
// ---------------------------------------------------------------------------
__global__ void __launch_bounds__(512) scores_kernel(const float* __restrict__ cls) {
    __shared__ float part[RPB * 20];

    const int t = threadIdx.x;
    if (blockIdx.x == 0 && t < BATCH) g_flag[t] = 0u;

    const float4* base = (const float4*)cls + (size_t)blockIdx.x * (RPB * 20);
    #pragma unroll
    for (int i = 0; i < 5; ++i) {
        int idx = t + 512 * i;
        float4 v = __ldg(&base[idx]);
        part[idx] = fmaxf(fmaxf(v.x, v.y), fmaxf(v.z, v.w));
    }
    __syncthreads();
    {
        int row = t >> 2;
        int p   = t & 3;
        const float* q = &part[row * 20 + p * 5];
        float m = q[0];
        #pragma unroll
        for (int j = 1; j < 5; ++j) m = fmaxf(m, q[j]);
        m = fmaxf(m, __shfl_xor_sync(0xFFFFFFFFu, m, 1));
        m = fmaxf(m, __shfl_xor_sync(0xFFFFFFFFu, m, 2));
        if (p == 0)
            g_scores_u[blockIdx.x * RPB + row] = f32_sortable(m);
    }
}

// ---------------------------------------------------------------------------
// Kernel 2 (combined): blocks 0..31 = per-batch top-300 (streaming re-reads,
// low regs); blocks 32..1231 = gather warps that spin on their batch's flag.
// Topk: quaternary threshold search over [min,max] 22-bit codes, block-scan
// compaction, sync-free all-vs-all ranking (key = score<<32 | SEQ-1-s).
// ---------------------------------------------------------------------------
__global__ void __launch_bounds__(256, 8) topk_gather_kernel(
        const float* __restrict__ cls,
        const float* __restrict__ coord,
        const float* __restrict__ mem,
        float* __restrict__ out) {
    const int t    = threadIdx.x;
    const int lane = t & 31;
    const int wid  = t >> 5;
    const unsigned FULL = 0xFFFFFFFFu;

    float* out_tgt  = out + (size_t)BATCH * NQ * 4;
    float* out_log  = out_tgt + (size_t)BATCH * NQ * DIM;
    float* out_bbox = out_log + (size_t)BATCH * NQ * NLAB;

    if (blockIdx.x < NTOPK) {
        // ==================== TOPK BRANCH ====================
        __shared__ unsigned int       s_w1[2][8];
        __shared__ unsigned int       s_w2[2][8];
        __shared__ unsigned int       s_woff[8];
        __shared__ unsigned int       s_cnt;
        __shared__ unsigned long long s_cand[CAND];

        const int batch = blockIdx.x;
        const unsigned int* sc  = g_scores_u + batch * SEQ;
        const uint4*        sc4 = (const uint4*)sc;   // 2100 uint4

        // ---- pass 1: block min/max (loads populate L1 for later passes) ----
        unsigned int mx = 0, mn = 0xFFFFFFFFu;
        #pragma unroll 4
        for (int k = 0; k < 8; ++k) {
            uint4 v = __ldg(&sc4[t + 256 * k]);
            mx = max(mx, max(max(v.x, v.y), max(v.z, v.w)));
            mn = min(mn, min(min(v.x, v.y), min(v.z, v.w)));
        }
        if (t < 52) {
            uint4 v = __ldg(&sc4[2048 + t]);
            mx = max(mx, max(max(v.x, v.y), max(v.z, v.w)));
            mn = min(mn, min(min(v.x, v.y), min(v.z, v.w)));
        }
        #pragma unroll
        for (int o = 16; o > 0; o >>= 1) {
            mx = max(mx, __shfl_xor_sync(FULL, mx, o));
            mn = min(mn, __shfl_xor_sync(FULL, mn, o));
        }
        if (lane == 0) { s_w1[0][wid] = mx; s_w2[0][wid] = mn; }
        __syncthreads();
        unsigned int a0 = (lane < 8) ? s_w1[0][lane] : 0u;
        unsigned int b0 = (lane < 8) ? s_w2[0][lane] : 0xFFFFFFFFu;
        #pragma unroll
        for (int o = 4; o > 0; o >>= 1) {
            a0 = max(a0, __shfl_xor_sync(FULL, a0, o));
            b0 = min(b0, __shfl_xor_sync(FULL, b0, o));
        }
        const unsigned int M    = __shfl_sync(FULL, a0, 0);
        const unsigned int m_lo = __shfl_sync(FULL, b0, 0);

        // ---- quaternary search on 22-bit codes (streaming, L1-hit) ----
        unsigned int lo = m_lo >> 10, hi = (M >> 10) + 1;
        int parity = 1;
        while (hi - lo > 1) {
            unsigned int d  = hi - lo;
            unsigned int m1 = lo + (d >> 2); if (m1 == lo) m1 = lo + 1;
            unsigned int m2 = lo + (d >> 1); if (m2 == lo) m2 = lo + 1;
            unsigned int m3 = lo + d - (d >> 2); if (m3 >= hi) m3 = hi - 1;
            const unsigned int t1 = m1 << 10, t2 = m2 << 10, t3 = m3 << 10;

            unsigned int c12 = 0, c3 = 0;
            #pragma unroll 4
            for (int k = 0; k < 8; ++k) {
                uint4 v = __ldg(&sc4[t + 256 * k]);
                c12 += (v.x >= t1) + (v.y >= t1) + (v.z >= t1) + (v.w >= t1);
                c12 += ((v.x >= t2) + (v.y >= t2) + (v.z >= t2) + (v.w >= t2)) << 16;
                c3  += (v.x >= t3) + (v.y >= t3) + (v.z >= t3) + (v.w >= t3);
            }
            if (t < 52) {
                uint4 v = __ldg(&sc4[2048 + t]);
                c12 += (v.x >= t1) + (v.y >= t1) + (v.z >= t1) + (v.w >= t1);
                c12 += ((v.x >= t2) + (v.y >= t2) + (v.z >= t2) + (v.w >= t2)) << 16;
                c3  += (v.x >= t3) + (v.y >= t3) + (v.z >= t3) + (v.w >= t3);
            }
            #pragma unroll
            for (int o = 16; o > 0; o >>= 1) {
                c12 += __shfl_xor_sync(FULL, c12, o);
                c3  += __shfl_xor_sync(FULL, c3,  o);
            }
            if (lane == 0) { s_w1[parity][wid] = c12; s_w2[parity][wid] = c3; }
            __syncthreads();
            unsigned int a = (lane < 8) ? s_w1[parity][lane] : 0u;
            unsigned int b = (lane < 8) ? s_w2[parity][lane] : 0u;
            #pragma unroll
            for (int o = 4; o > 0; o >>= 1) {
                a += __shfl_xor_sync(FULL, a, o);
                b += __shfl_xor_sync(FULL, b, o);
            }
            a = __shfl_sync(FULL, a, 0);
            b = __shfl_sync(FULL, b, 0);
            const unsigned int cnt1 = a & 0xFFFFu;
            const unsigned int cnt2 = a >> 16;
            const unsigned int cnt3 = b;

            if      (cnt3 >= NQ) lo = m3;
            else if (cnt2 >= NQ) { lo = m2; hi = m3; }
            else if (cnt1 >= NQ) { lo = m1; hi = m2; }
            else                 hi = m1;
            parity ^= 1;
        }
        const unsigned int T = lo << 10;

        // ---- count my hits, block prefix scan ----
        int myc = 0;
        #pragma unroll 4
        for (int k = 0; k < 8; ++k) {
            uint4 v = __ldg(&sc4[t + 256 * k]);
            myc += (v.x >= T) + (v.y >= T) + (v.z >= T) + (v.w >= T);
        }
        if (t < 52) {
            uint4 v = __ldg(&sc4[2048 + t]);
            myc += (v.x >= T) + (v.y >= T) + (v.z >= T) + (v.w >= T);
        }
        int inc = myc;
        #pragma unroll
        for (int o = 1; o < 32; o <<= 1) {
            int t2 = __shfl_up_sync(FULL, inc, o);
            if (lane >= o) inc += t2;
        }
        __syncthreads();
        if (lane == 31) s_w1[0][wid] = (unsigned)inc;
        __syncthreads();
        if (t < 8) {
            unsigned int v = s_w1[0][t];
            unsigned int i2 = v;
            #pragma unroll
            for (int o = 1; o < 8; o <<= 1) {
                unsigned int t2 = __shfl_up_sync(0xFFu, i2, o);
                if (t >= o) i2 += t2;
            }
            s_woff[t] = i2 - v;
            if (t == 7) s_cnt = i2;
        }
        __syncthreads();

        // ---- emit candidates (same traversal order as the count pass) ----
        int pos = (int)s_woff[wid] + (inc - myc);
        #pragma unroll 4
        for (int k = 0; k < 8; ++k) {
            uint4 v = __ldg(&sc4[t + 256 * k]);
            const unsigned int vals[4] = { v.x, v.y, v.z, v.w };
            #pragma unroll
            for (int j = 0; j < 4; ++j) {
                if (vals[j] >= T) {
                    int idx = 4 * (t + 256 * k) + j;
                    if (pos < CAND)
                        s_cand[pos] = ((unsigned long long)vals[j] << 32) |
                                      (unsigned int)(SEQ - 1 - idx);
                    ++pos;
                }
            }
        }
        if (t < 52) {
            uint4 v = __ldg(&sc4[2048 + t]);
            const unsigned int vals[4] = { v.x, v.y, v.z, v.w };
            #pragma unroll
            for (int j = 0; j < 4; ++j) {
                if (vals[j] >= T) {
                    int idx = 8192 + 4 * t + j;
                    if (pos < CAND)
                        s_cand[pos] = ((unsigned long long)vals[j] << 32) |
                                      (unsigned int)(SEQ - 1 - idx);
                    ++pos;
                }
            }
        }
        __syncthreads();

        // ---- sync-free ranking ----
        const int cntC = (int)min(s_cnt, (unsigned)CAND);
        for (int c = t; c < cntC; c += 256) {
            const unsigned long long mine = s_cand[c];
            int rank = 0;
            for (int j = 0; j < cntC; ++j)
                rank += (s_cand[j] > mine);
            if (rank < NQ)
                g_topk[batch * NQ + rank] =
                    SEQ - 1 - (int)(unsigned int)(mine & 0xFFFFFFFFull);
        }

        __syncthreads();
        if (t == 0) {
            __threadfence();                      // 32 blocks only: cheap
            asm volatile("st.release.gpu.u32 [%0], %1;"
                         :: "l"(&g_flag[batch]), "r"(1u) : "memory");
        }
        return;
    }

    // ==================== GATHER BRANCH ====================
    const int bq    = (blockIdx.x - NTOPK) * 8 + wid;   // one warp per query
    const int batch = bq / NQ;

    if (lane == 0) {
        while (ld_acquire(&g_flag[batch]) == 0u) __nanosleep(200);
    }
    __syncwarp();

    const int s = ld_cg_s32(&g_topk[bq]);
    const size_t src = (size_t)batch * SEQ + (size_t)s;

    float4 lg, cd;
    if (lane < 20)
        lg = __ldg(&((const float4*)(cls + src * NLAB))[lane]);
    if (lane == 20)
        cd = __ldg((const float4*)(coord + src * 4));
    const float4* m4 = (const float4*)(mem + src * DIM);
    float4 m0 = __ldg(&m4[lane]);
    float4 m1 = __ldg(&m4[lane + 32]);

    float* o = out_tgt + (size_t)bq * DIM;
    stg_cs_f4(o + 4 * lane,        m0);
    stg_cs_f4(o + 4 * (lane + 32), m1);
    if (lane < 20)
        stg_cs_f4(out_log + (size_t)bq * NLAB + 4 * lane, lg);
    if (lane == 20) {
        stg_cs_f4(out + (size_t)bq * 4, cd);
        float4 sg;
        sg.x = 1.0f / (1.0f + __expf(-cd.x));
        sg.y = 1.0f / (1.0f + __expf(-cd.y));
        sg.z = 1.0f / (1.0f + __expf(-cd.z));
        sg.w = 1.0f / (1.0f + __expf(-cd.w));
        stg_cs_f4(out_bbox + (size_t)bq * 4, sg);
    }
}

// ---------------------------------------------------------------------------
extern "C" void kernel_launch(void* const* d_in, const int* in_sizes, int n_in,
                              void* d_out, int out_size) {
    const float* cls   = (const float*)d_in[0];  // (32, 8400, 80)
    const float* coord = (const float*)d_in[1];  // (32, 8400, 4)
    const float* mem   = (const float*)d_in[2];  // (32, 8400, 256)
    float* out = (float*)d_out;

    scores_kernel<<<(BATCH * SEQ) / RPB, 512>>>(cls);              // 2100 blocks
    topk_gather_kernel<<<NTOPK + NGATH, 256>>>(cls, coord, mem, out); // 1232 blocks
}

// round 13
// speedup vs baseline: 1.6388x; 1.6388x over previous
#include <cuda_runtime.h>
#include <stdint.h>
#include <math.h>

#define BATCH 32
#define SEQ   8400
#define NLAB  80
#define DIM   256
#define NQ    300
#define CAND  512
#define RPB   128     // rows per block in scores kernel (512 thr, 5 ld/thread)
#define NTOPK BATCH
#define NGATH ((BATCH * NQ) / 8)   // 1200 gather blocks (8 queries each)

// Scratch (allocation-free per harness rules)
__device__ unsigned int g_scores_u[BATCH * SEQ];
__device__ int          g_topk[BATCH * NQ];
__device__ unsigned int g_flag[BATCH];            // zero-init; reset by scores

__device__ __forceinline__ unsigned int f32_sortable(float v) {
    unsigned int u = __float_as_uint(v);
    return (u & 0x80000000u) ? ~u : (u | 0x80000000u);
}
__device__ __forceinline__ void stg_cs_f4(float* p, float4 v) {
    asm volatile("st.global.cs.v4.f32 [%0], {%1,%2,%3,%4};"
                 :: "l"(p), "f"(v.x), "f"(v.y), "f"(v.z), "f"(v.w) : "memory");
}
// relaxed gpu-scope load: L2 visit, NO L1 invalidation (poll-safe)
__device__ __forceinline__ unsigned int ld_relaxed(const unsigned int* p) {
    unsigned int v;
    asm volatile("ld.relaxed.gpu.u32 %0, [%1];" : "=r"(v) : "l"(p) : "memory");
    return v;
}
// single acquire load for ordering once the relaxed poll sees the flag
__device__ __forceinline__ unsigned int ld_acquire(const unsigned int* p) {
    unsigned int v;
    asm volatile("ld.acquire.gpu.u32 %0, [%1];" : "=r"(v) : "l"(p) : "memory");
    return v;
}
// L2-only data load (g_topk lines straddle batch boundaries -> L1 unsafe)
__device__ __forceinline__ int ld_cg_s32(const int* p) {
    int v;
    asm volatile("ld.global.cg.s32 %0, [%1];" : "=r"(v) : "l"(p));
    return v;
}

// ---------------------------------------------------------------------------
// Kernel 1: scores (best measured: 512 thr, 5 float4/thread, smem transpose).
// Block 0 resets the handshake flags (kernel boundary = fence for kernel 2).
// ---------------------------------------------------------------------------
__global__ void __launch_bounds__(512) scores_kernel(const float* __restrict__ cls) {
    __shared__ float part[RPB * 20];

    const int t = threadIdx.x;
    if (blockIdx.x == 0 && t < BATCH) g_flag[t] = 0u;

    const float4* base = (const float4*)cls + (size_t)blockIdx.x * (RPB * 20);
    #pragma unroll
    for (int i = 0; i < 5; ++i) {
        int idx = t + 512 * i;
        float4 v = __ldg(&base[idx]);
        part[idx] = fmaxf(fmaxf(v.x, v.y), fmaxf(v.z, v.w));
    }
    __syncthreads();
    {
        int row = t >> 2;
        int p   = t & 3;
        const float* q = &part[row * 20 + p * 5];
        float m = q[0];
        #pragma unroll
        for (int j = 1; j < 5; ++j) m = fmaxf(m, q[j]);
        m = fmaxf(m, __shfl_xor_sync(0xFFFFFFFFu, m, 1));
        m = fmaxf(m, __shfl_xor_sync(0xFFFFFFFFu, m, 2));
        if (p == 0)
            g_scores_u[blockIdx.x * RPB + row] = f32_sortable(m);
    }
}

// ---------------------------------------------------------------------------
// Kernel 2 (combined): blocks 0..31 = per-batch top-300; blocks 32..1231 =
// gather (one warp per query). Handshake: topk block b does threadfence +
// st.release(g_flag[b]); gather blocks poll with RELAXED loads (thread 0
// only, nanosleep backoff), then one acquire load, then __syncthreads.
// ---------------------------------------------------------------------------
__global__ void __launch_bounds__(256, 8) topk_gather_kernel(
        const float* __restrict__ cls,
        const float* __restrict__ coord,
        const float* __restrict__ mem,
        float* __restrict__ out) {
    const int t    = threadIdx.x;
    const int lane = t & 31;
    const int wid  = t >> 5;
    const unsigned FULL = 0xFFFFFFFFu;

    float* out_tgt  = out + (size_t)BATCH * NQ * 4;
    float* out_log  = out_tgt + (size_t)BATCH * NQ * DIM;
    float* out_bbox = out_log + (size_t)BATCH * NQ * NLAB;

    if (blockIdx.x < NTOPK) {
        // ==================== TOPK BRANCH (one block per batch) ============
        __shared__ unsigned int       s_w1[2][8];
        __shared__ unsigned int       s_w2[2][8];
        __shared__ unsigned int       s_woff[8];
        __shared__ unsigned int       s_cnt;
        __shared__ unsigned long long s_cand[CAND];

        const int batch = blockIdx.x;
        const uint4* sc4 = (const uint4*)(g_scores_u + batch * SEQ);  // 2100

        // ---- pass 1: block min/max (loads warm L1 for later passes) ----
        unsigned int mx = 0, mn = 0xFFFFFFFFu;
        #pragma unroll 4
        for (int k = 0; k < 8; ++k) {
            uint4 v = __ldg(&sc4[t + 256 * k]);
            mx = max(mx, max(max(v.x, v.y), max(v.z, v.w)));
            mn = min(mn, min(min(v.x, v.y), min(v.z, v.w)));
        }
        if (t < 52) {
            uint4 v = __ldg(&sc4[2048 + t]);
            mx = max(mx, max(max(v.x, v.y), max(v.z, v.w)));
            mn = min(mn, min(min(v.x, v.y), min(v.z, v.w)));
        }
        #pragma unroll
        for (int o = 16; o > 0; o >>= 1) {
            mx = max(mx, __shfl_xor_sync(FULL, mx, o));
            mn = min(mn, __shfl_xor_sync(FULL, mn, o));
        }
        if (lane == 0) { s_w1[0][wid] = mx; s_w2[0][wid] = mn; }
        __syncthreads();
        unsigned int a0 = (lane < 8) ? s_w1[0][lane] : 0u;
        unsigned int b0 = (lane < 8) ? s_w2[0][lane] : 0xFFFFFFFFu;
        #pragma unroll
        for (int o = 4; o > 0; o >>= 1) {
            a0 = max(a0, __shfl_xor_sync(FULL, a0, o));
            b0 = min(b0, __shfl_xor_sync(FULL, b0, o));
        }
        const unsigned int M    = __shfl_sync(FULL, a0, 0);
        const unsigned int m_lo = __shfl_sync(FULL, b0, 0);

        // ---- quaternary search on 22-bit codes (L1-hit streaming) ----
        unsigned int lo = m_lo >> 10, hi = (M >> 10) + 1;
        int parity = 1;
        while (hi - lo > 1) {
            unsigned int d  = hi - lo;
            unsigned int m1 = lo + (d >> 2); if (m1 == lo) m1 = lo + 1;
            unsigned int m2 = lo + (d >> 1); if (m2 == lo) m2 = lo + 1;
            unsigned int m3 = lo + d - (d >> 2); if (m3 >= hi) m3 = hi - 1;
            const unsigned int t1 = m1 << 10, t2 = m2 << 10, t3 = m3 << 10;

            unsigned int c12 = 0, c3 = 0;
            #pragma unroll 4
            for (int k = 0; k < 8; ++k) {
                uint4 v = __ldg(&sc4[t + 256 * k]);
                c12 += (v.x >= t1) + (v.y >= t1) + (v.z >= t1) + (v.w >= t1);
                c12 += ((v.x >= t2) + (v.y >= t2) + (v.z >= t2) + (v.w >= t2)) << 16;
                c3  += (v.x >= t3) + (v.y >= t3) + (v.z >= t3) + (v.w >= t3);
            }
            if (t < 52) {
                uint4 v = __ldg(&sc4[2048 + t]);
                c12 += (v.x >= t1) + (v.y >= t1) + (v.z >= t1) + (v.w >= t1);
                c12 += ((v.x >= t2) + (v.y >= t2) + (v.z >= t2) + (v.w >= t2)) << 16;
                c3  += (v.x >= t3) + (v.y >= t3) + (v.z >= t3) + (v.w >= t3);
            }
            #pragma unroll
            for (int o = 16; o > 0; o >>= 1) {
                c12 += __shfl_xor_sync(FULL, c12, o);
                c3  += __shfl_xor_sync(FULL, c3,  o);
            }
            if (lane == 0) { s_w1[parity][wid] = c12; s_w2[parity][wid] = c3; }
            __syncthreads();
            unsigned int a = (lane < 8) ? s_w1[parity][lane] : 0u;
            unsigned int b = (lane < 8) ? s_w2[parity][lane] : 0u;
            #pragma unroll
            for (int o = 4; o > 0; o >>= 1) {
                a += __shfl_xor_sync(FULL, a, o);
                b += __shfl_xor_sync(FULL, b, o);
            }
            a = __shfl_sync(FULL, a, 0);
            b = __shfl_sync(FULL, b, 0);
            const unsigned int cnt1 = a & 0xFFFFu;
            const unsigned int cnt2 = a >> 16;
            const unsigned int cnt3 = b;

            if      (cnt3 >= NQ) lo = m3;
            else if (cnt2 >= NQ) { lo = m2; hi = m3; }
            else if (cnt1 >= NQ) { lo = m1; hi = m2; }
            else                 hi = m1;
            parity ^= 1;
        }
        const unsigned int T = lo << 10;

        // ---- count hits + block prefix scan ----
        int myc = 0;
        #pragma unroll 4
        for (int k = 0; k < 8; ++k) {
            uint4 v = __ldg(&sc4[t + 256 * k]);
            myc += (v.x >= T) + (v.y >= T) + (v.z >= T) + (v.w >= T);
        }
        if (t < 52) {
            uint4 v = __ldg(&sc4[2048 + t]);
            myc += (v.x >= T) + (v.y >= T) + (v.z >= T) + (v.w >= T);
        }
        int inc = myc;
        #pragma unroll
        for (int o = 1; o < 32; o <<= 1) {
            int t2 = __shfl_up_sync(FULL, inc, o);
            if (lane >= o) inc += t2;
        }
        __syncthreads();
        if (lane == 31) s_w1[0][wid] = (unsigned)inc;
        __syncthreads();
        if (t < 8) {
            unsigned int v = s_w1[0][t];
            unsigned int i2 = v;
            #pragma unroll
            for (int o = 1; o < 8; o <<= 1) {
                unsigned int t2 = __shfl_up_sync(0xFFu, i2, o);
                if (t >= o) i2 += t2;
            }
            s_woff[t] = i2 - v;
            if (t == 7) s_cnt = i2;
        }
        __syncthreads();

        // ---- emit candidates ----
        int pos = (int)s_woff[wid] + (inc - myc);
        #pragma unroll 4
        for (int k = 0; k < 8; ++k) {
            uint4 v = __ldg(&sc4[t + 256 * k]);
            const unsigned int vals[4] = { v.x, v.y, v.z, v.w };
            #pragma unroll
            for (int j = 0; j < 4; ++j) {
                if (vals[j] >= T) {
                    int idx = 4 * (t + 256 * k) + j;
                    if (pos < CAND)
                        s_cand[pos] = ((unsigned long long)vals[j] << 32) |
                                      (unsigned int)(SEQ - 1 - idx);
                    ++pos;
                }
            }
        }
        if (t < 52) {
            uint4 v = __ldg(&sc4[2048 + t]);
            const unsigned int vals[4] = { v.x, v.y, v.z, v.w };
            #pragma unroll
            for (int j = 0; j < 4; ++j) {
                if (vals[j] >= T) {
                    int idx = 8192 + 4 * t + j;
                    if (pos < CAND)
                        s_cand[pos] = ((unsigned long long)vals[j] << 32) |
                                      (unsigned int)(SEQ - 1 - idx);
                    ++pos;
                }
            }
        }
        __syncthreads();

        // ---- sync-free ranking ----
        const int cntC = (int)min(s_cnt, (unsigned)CAND);
        for (int c = t; c < cntC; c += 256) {
            const unsigned long long mine = s_cand[c];
            int rank = 0;
            for (int j = 0; j < cntC; ++j)
                rank += (s_cand[j] > mine);
            if (rank < NQ)
                g_topk[batch * NQ + rank] =
                    SEQ - 1 - (int)(unsigned int)(mine & 0xFFFFFFFFull);
        }

        __syncthreads();
        if (t == 0) {
            __threadfence();                      // 32 threads total: cheap
            asm volatile("st.release.gpu.u32 [%0], %1;"
                         :: "l"(&g_flag[batch]), "r"(1u) : "memory");
        }
        return;
    }

    // ==================== GATHER BRANCH ====================
    const int gblk = blockIdx.x - NTOPK;
    const int bq   = gblk * 8 + wid;              // one warp per query
    const int batch = bq / NQ;

    // thread-0-only RELAXED poll (no L1 invalidation), then one acquire.
    if (t == 0) {
        const int bA = (gblk * 8) / NQ;
        const int bB = (gblk * 8 + 7) / NQ;
        while (ld_relaxed(&g_flag[bA]) == 0u) __nanosleep(300);
        if (bB != bA)
            while (ld_relaxed(&g_flag[bB]) == 0u) __nanosleep(300);
        (void)ld_acquire(&g_flag[bA]);            // ordering
    }
    __syncthreads();

    const int s = ld_cg_s32(&g_topk[bq]);         // L2-only (L1 unsafe here)
    const size_t src = (size_t)batch * SEQ + (size_t)s;

    float4 lg, cd;
    if (lane < 20)
        lg = __ldg(&((const float4*)(cls + src * NLAB))[lane]);
    if (lane == 20)
        cd = __ldg((const float4*)(coord + src * 4));
    const float4* m4 = (const float4*)(mem + src * DIM);
    float4 m0 = __ldg(&m4[lane]);
    float4 m1 = __ldg(&m4[lane + 32]);

    float* o = out_tgt + (size_t)bq * DIM;
    stg_cs_f4(o + 4 * lane,        m0);
    stg_cs_f4(o + 4 * (lane + 32), m1);
    if (lane < 20)
        stg_cs_f4(out_log + (size_t)bq * NLAB + 4 * lane, lg);
    if (lane == 20) {
        stg_cs_f4(out + (size_t)bq * 4, cd);
        float4 sg;
        sg.x = 1.0f / (1.0f + __expf(-cd.x));
        sg.y = 1.0f / (1.0f + __expf(-cd.y));
        sg.z = 1.0f / (1.0f + __expf(-cd.z));
        sg.w = 1.0f / (1.0f + __expf(-cd.w));
        stg_cs_f4(out_bbox + (size_t)bq * 4, sg);
    }
}

// ---------------------------------------------------------------------------
extern "C" void kernel_launch(void* const* d_in, const int* in_sizes, int n_in,
                              void* d_out, int out_size) {
    const float* cls   = (const float*)d_in[0];  // (32, 8400, 80)
    const float* coord = (const float*)d_in[1];  // (32, 8400, 4)
    const float* mem   = (const float*)d_in[2];  // (32, 8400, 256)
    float* out = (float*)d_out;

    scores_kernel<<<(BATCH * SEQ) / RPB, 512>>>(cls);                 // 2100
    topk_gather_kernel<<<NTOPK + NGATH, 256>>>(cls, coord, mem, out); // 1232
}